// round 15
// baseline (speedup 1.0000x reference)
#include <cuda_runtime.h>
#include <cstddef>

// DilatedKNN: B=4, N=8192, C=64, K=9, d=2 -> top-18 nearest, slice ::2.
// Output float32. key = max((|s|^2+|q|^2) - 2*dot, 0).
// INVARIANT (R14 lesson): every dot = ONE sequential fmaf/fma2 chain over
// ascending k; norms = same sequential chain. Keys bit-identical to R13
// (rel_err must reproduce 7.627561e-4).
//
// R15: ratio attack. TSC=256, CP=8, JP=4: 16 LDS.128 -> 128 fma2 per k2
// (ratio 8 vs R13's 5.3). unroll 8 -> imm-offset LDS (kill alu IMADs).
// Norms precomputed once into __device__ g_sq (same chain, bit-identical).

#define BATCH 4
#define NPTS  8192
#define CDIM  64
#define KOUT  9
#define KK    18
#define MQ    64      // queries per block
#define TSC   256     // candidate tile rows
#define TPB   128
#define NK2   32

// smem floats:
//  qs : 32 k2 x 33 u2 = 4224       @ 0
//  qw : swapped copy  = 4224       @ 4224
//  U  : 16576 @ 8448: ssm 32 k2 x 129 u2 (16512) [phase A]
//                     d2s 64 x 259 (16576)       [phase B]
//                     merge lists (4608)         [epilogue]
//  sS : 256 @ 25024
#define SM_QW     4224
#define SM_U      8448
#define SM_SS     25024
#define SM_FLOATS 25280

__device__ float g_sq[BATCH * NPTS];

__device__ __forceinline__ void fma2(unsigned long long& d,
                                     unsigned long long a,
                                     unsigned long long b) {
    asm("fma.rn.f32x2 %0, %1, %2, %0;" : "+l"(d) : "l"(a), "l"(b));
}
__device__ __forceinline__ float2 unpack2(unsigned long long v) {
    float2 r;
    asm("mov.b64 {%0, %1}, %2;" : "=f"(r.x), "=f"(r.y) : "l"(v));
    return r;
}

// ---- norms: one thread per row, sequential ascending-k fmaf chain ----
__global__ void __launch_bounds__(256) sq_kernel(const float* __restrict__ q) {
    int r = blockIdx.x * 256 + threadIdx.x;
    if (r >= BATCH * NPTS) return;
    const float* row = q + (size_t)r * CDIM;
    float s = 0.f;
#pragma unroll
    for (int c = 0; c < CDIM; c++) s = fmaf(row[c], row[c], s);
    g_sq[r] = s;
}

__global__ void __launch_bounds__(TPB, 2)
knn_kernel(const float* __restrict__ q, float* __restrict__ out) {
    extern __shared__ float smem[];
    float4*     qs4 = (float4*)smem;
    ulonglong2* qsU = (ulonglong2*)smem;
    float4*     qw4 = (float4*)(smem + SM_QW);
    ulonglong2* qwU = (ulonglong2*)(smem + SM_QW);
    float4*     ss4 = (float4*)(smem + SM_U);
    ulonglong2* ssU = (ulonglong2*)(smem + SM_U);
    float*      d2s = smem + SM_U;            // aliases ssm (phase B)
    float*      sS  = smem + SM_SS;

    const int b  = blockIdx.x >> 7;           // 128 blocks per batch
    const int q0 = (blockIdx.x & 127) * MQ;
    const float* qb = q + (size_t)b * NPTS * CDIM;
    const int tid = threadIdx.x;
    const int tx  = tid & 15;                 // cpairs tx+16*cp (cp 0..7)
    const int ty  = tid >> 4;                 // qpairs ty+8*jp  (jp 0..3)
    const int qi  = tid & 63;                 // phase-B query
    const int h   = tid >> 6;                 // phase-B half (0/1)

    // ---- query tile: pair-interleaved + swapped copy ----
    for (int t = tid; t < 32 * 16; t += TPB) {
        int p = t >> 4, kc = t & 15;
        float4 a = ((const float4*)(qb + (size_t)(q0 + 2 * p) * CDIM))[kc];
        float4 c = ((const float4*)(qb + (size_t)(q0 + 2 * p + 1) * CDIM))[kc];
        qs4[(2 * kc) * 33 + p]     = make_float4(a.x, c.x, a.y, c.y);
        qs4[(2 * kc + 1) * 33 + p] = make_float4(a.z, c.z, a.w, c.w);
        qw4[(2 * kc) * 33 + p]     = make_float4(c.x, a.x, c.y, a.y);
        qw4[(2 * kc + 1) * 33 + p] = make_float4(c.z, a.z, c.w, a.w);
    }
    const float sqm = g_sq[b * NPTS + q0 + qi];

    float kd[KK];
    int   ki[KK];
#pragma unroll
    for (int j = 0; j < KK; j++) { kd[j] = 3.402823466e38f; ki[j] = 0; }
    __syncthreads();

    for (int c0 = 0; c0 < NPTS; c0 += TSC) {
        // ---- candidate tile: 128 cpairs x 16 kq, pair-interleaved ----
        for (int t = tid; t < 128 * 16; t += TPB) {
            int p = t >> 4, kc = t & 15;
            float4 a = ((const float4*)(qb + (size_t)(c0 + 2 * p) * CDIM))[kc];
            float4 c = ((const float4*)(qb + (size_t)(c0 + 2 * p + 1) * CDIM))[kc];
            ss4[(2 * kc) * 129 + p]     = make_float4(a.x, c.x, a.y, c.y);
            ss4[(2 * kc + 1) * 129 + p] = make_float4(a.z, c.z, a.w, c.w);
        }
        for (int i = tid; i < TSC; i += TPB)
            sS[i] = g_sq[b * NPTS + c0 + i];
        __syncthreads();   // tile + norms visible

        // ---- phase A: 8q x 16c packed dots (ratio: 16 LDS -> 128 fma2) ----
        unsigned long long accA[4][8], accB[4][8];
#pragma unroll
        for (int jp = 0; jp < 4; jp++)
#pragma unroll
            for (int cp = 0; cp < 8; cp++) { accA[jp][cp] = 0ull; accB[jp][cp] = 0ull; }

#pragma unroll 8
        for (int k2 = 0; k2 < NK2; k2++) {
            ulonglong2 qa[4], qw[4], sv[8];
#pragma unroll
            for (int jp = 0; jp < 4; jp++) {
                qa[jp] = qsU[k2 * 33 + ty + 8 * jp];
                qw[jp] = qwU[k2 * 33 + ty + 8 * jp];
            }
#pragma unroll
            for (int cp = 0; cp < 8; cp++) sv[cp] = ssU[k2 * 129 + tx + 16 * cp];
#pragma unroll
            for (int jp = 0; jp < 4; jp++)
#pragma unroll
                for (int cp = 0; cp < 8; cp++) {
                    fma2(accA[jp][cp], qa[jp].x, sv[cp].x);  // (qe*ce, qo*co) k
                    fma2(accA[jp][cp], qa[jp].y, sv[cp].y);  //               k+1
                    fma2(accB[jp][cp], qw[jp].x, sv[cp].x);  // (qo*ce, qe*co) k
                    fma2(accB[jp][cp], qw[jp].y, sv[cp].y);  //               k+1
                }
        }
        __syncthreads();   // all phase-A reads of ssm done -> becomes d2s

        // ---- transpose dots into d2s[q*259 + c] ----
#pragma unroll
        for (int jp = 0; jp < 4; jp++)
#pragma unroll
            for (int cp = 0; cp < 8; cp++) {
                float2 A  = unpack2(accA[jp][cp]);  // (qe.ce, qo.co)
                float2 Bv = unpack2(accB[jp][cp]);  // (qo.ce, qe.co)
                int qe = 2 * (ty + 8 * jp);
                int ce = 2 * (tx + 16 * cp);
                *(float2*)(d2s + qe * 259 + ce) = make_float2(A.x, Bv.y); // even row 8B-aligned
                d2s[(qe + 1) * 259 + ce]     = Bv.x;   // odd row: scalar (align)
                d2s[(qe + 1) * 259 + ce + 1] = A.y;
            }
        __syncthreads();   // dots visible

        // ---- phase B: my half-row (128 candidates) ----
        const float* row = d2s + qi * 259 + h * 128;
        const float* ns  = sS + h * 128;
        const int base = c0 + h * 128;
#pragma unroll 4
        for (int s = 0; s < 128; s++) {
            float t   = ns[s] + sqm;
            float d2  = t - 2.0f * row[s];
            float key = fmaxf(d2, 0.0f);
            if (key < kd[KK - 1]) {
                kd[KK - 1] = key;
                ki[KK - 1] = base + s;
#pragma unroll
                for (int j = KK - 1; j >= 1; --j) {
                    if (kd[j] < kd[j - 1]) {
                        float tk = kd[j]; kd[j] = kd[j - 1]; kd[j - 1] = tk;
                        int   ti = ki[j]; ki[j] = ki[j - 1]; ki[j - 1] = ti;
                    }
                }
            }
        }
        __syncthreads();   // d2s consumed; next tile may overwrite
    }

    // ---- merge the two half-lists per query (stable by (key, idx)) ----
    float* mk = smem + SM_U;                // 128 slots x 18 keys
    int*   mi = (int*)(smem + SM_U + 2304); // 128 slots x 18 idx
    {
        int slot = qi * 2 + h;
#pragma unroll
        for (int j = 0; j < KK; j++) {
            mk[slot * KK + j] = kd[j];
            mi[slot * KK + j] = ki[j];
        }
    }
    __syncthreads();
    if (tid < MQ) {
        const float* ka = mk + (tid * 2) * KK;
        const int*   ia = mi + (tid * 2) * KK;
        const float* kb = ka + KK;
        const int*   ib = ia + KK;
        float* orow = out + ((size_t)(b * NPTS + q0 + tid)) * KOUT;
        int pa = 0, pb = 0;
#pragma unroll
        for (int j = 0; j < KK; j++) {
            float k0 = ka[pa], k1 = kb[pb];
            int   i0 = ia[pa], i1 = ib[pb];
            bool takeA = (k0 < k1) || (k0 == k1 && i0 < i1);
            int sel = takeA ? i0 : i1;
            if ((j & 1) == 0) orow[j >> 1] = (float)sel;   // dilated ::2
            pa += takeA ? 1 : 0;
            pb += takeA ? 0 : 1;
        }
    }
}

// ---------------------------------------------------------------------------
extern "C" void kernel_launch(void* const* d_in, const int* in_sizes, int n_in,
                              void* d_out, int out_size) {
    const float* q = (const float*)d_in[0];
    float* out = (float*)d_out;
    size_t smem_bytes = (size_t)SM_FLOATS * sizeof(float);   // ~98.8 KB
    cudaFuncSetAttribute(knn_kernel,
                         cudaFuncAttributeMaxDynamicSharedMemorySize,
                         (int)smem_bytes);
    sq_kernel<<<(BATCH * NPTS + 255) / 256, 256>>>(q);
    knn_kernel<<<BATCH * (NPTS / MQ), TPB, smem_bytes>>>(q, out);
}